// round 1
// baseline (speedup 1.0000x reference)
#include <cuda_runtime.h>
#include <math.h>

#define N_PTS 2048
#define B_SZ 4
#define KNN 20
#define PPOS (B_SZ * N_PTS * KNN)   // 163840
#define HCH 512
#define NEG_SLOPE 0.2f

// ---------------- scratch (static device globals; no runtime allocation) ----------------
__device__ float  g_pd[B_SZ * N_PTS * N_PTS];       // 64 MB
__device__ float  g_xx[B_SZ * N_PTS];
__device__ int    g_idx[B_SZ * N_PTS * KNN];
__device__ float  g_Y[256 * PPOS];                  // 168 MB  (o-major: Y[o*PPOS + pos])
__device__ float  g_H[B_SZ * HCH * N_PTS];          // 16 MB   (B, 512, N) concat buffer
__device__ float  g_Y5[1024 * 8192];                // 32 MB   (o-major: Y5[o*8192 + pos])
__device__ double g_sum[1024], g_sq[1024];
__device__ float  g_scale[1024], g_shift[1024];
__device__ float  g_z[B_SZ * 2048];
__device__ float  g_e[2 * B_SZ * 10];

// ---------------- xx[b,n] = sum_c f^2 ----------------
__global__ void compute_xx(const float* __restrict__ xin, int use_x, int choff,
                           int bstride, int Cin) {
    int i = blockIdx.x * blockDim.x + threadIdx.x;
    if (i >= B_SZ * N_PTS) return;
    int b = i / N_PTS, n = i % N_PTS;
    const float* f = (use_x ? xin : g_H) + (size_t)b * bstride + (size_t)choff * N_PTS + n;
    float s = 0.f;
    for (int c = 0; c < Cin; c++) { float v = f[(size_t)c * N_PTS]; s += v * v; }
    g_xx[i] = s;
}

// ---------------- pd[b,n,m] = 2*inner - xx[n] - xx[m] ----------------
__global__ void pd_gemm(const float* __restrict__ xin, int use_x, int choff,
                        int bstride, int Cin) {
    __shared__ float As[16][64];
    __shared__ float Bs[16][64];
    int b = blockIdx.z;
    int m0 = blockIdx.x * 64, n0 = blockIdx.y * 64;
    const float* f = (use_x ? xin : g_H) + (size_t)b * bstride + (size_t)choff * N_PTS;
    int tid = threadIdx.x, tx = tid & 15, ty = tid >> 4;
    float acc[4][4] = {};
    for (int c0 = 0; c0 < Cin; c0 += 16) {
#pragma unroll
        for (int l = 0; l < 4; l++) {
            int li = l * 256 + tid;
            int cl = li >> 6, j = li & 63;
            int c = c0 + cl;
            As[cl][j] = (c < Cin) ? f[(size_t)c * N_PTS + n0 + j] : 0.f;
            Bs[cl][j] = (c < Cin) ? f[(size_t)c * N_PTS + m0 + j] : 0.f;
        }
        __syncthreads();
#pragma unroll
        for (int kk = 0; kk < 16; kk++) {
            float4 a4 = *(const float4*)&As[kk][ty << 2];
            float4 b4 = *(const float4*)&Bs[kk][tx << 2];
            float a[4] = {a4.x, a4.y, a4.z, a4.w};
            float bb[4] = {b4.x, b4.y, b4.z, b4.w};
#pragma unroll
            for (int i = 0; i < 4; i++)
#pragma unroll
                for (int j = 0; j < 4; j++) acc[i][j] += a[i] * bb[j];
        }
        __syncthreads();
    }
    float xn[4], xm[4];
#pragma unroll
    for (int i = 0; i < 4; i++) xn[i] = g_xx[b * N_PTS + n0 + (ty << 2) + i];
#pragma unroll
    for (int j = 0; j < 4; j++) xm[j] = g_xx[b * N_PTS + m0 + (tx << 2) + j];
#pragma unroll
    for (int i = 0; i < 4; i++) {
        float4 o;
        o.x = 2.f * acc[i][0] - xn[i] - xm[0];
        o.y = 2.f * acc[i][1] - xn[i] - xm[1];
        o.z = 2.f * acc[i][2] - xn[i] - xm[2];
        o.w = 2.f * acc[i][3] - xn[i] - xm[3];
        *(float4*)&g_pd[(size_t)b * N_PTS * N_PTS + (size_t)(n0 + (ty << 2) + i) * N_PTS +
                        m0 + (tx << 2)] = o;
    }
}

// ---------------- top-20 per row (value desc, index asc on ties) ----------------
__global__ void topk_kernel() {
    int r = blockIdx.x;  // b*2048 + n
    const float* row = g_pd + (size_t)r * N_PTS;
    __shared__ unsigned long long keys[N_PTS];
    __shared__ unsigned long long red[256];
    int tid = threadIdx.x;
    for (int m = tid; m < N_PTS; m += 256) {
        unsigned u = __float_as_uint(row[m]);
        u = (u & 0x80000000u) ? ~u : (u | 0x80000000u);
        keys[m] = ((unsigned long long)u << 32) | (unsigned)(0xFFFFFFFFu - m);
    }
    __syncthreads();
    for (int it = 0; it < KNN; it++) {
        unsigned long long best = 0;
        for (int m = tid; m < N_PTS; m += 256) {
            unsigned long long k = keys[m];
            if (k > best) best = k;
        }
        red[tid] = best;
        __syncthreads();
        for (int st = 128; st; st >>= 1) {
            if (tid < st && red[tid + st] > red[tid]) red[tid] = red[tid + st];
            __syncthreads();
        }
        unsigned long long top = red[0];
        int midx = (int)(0xFFFFFFFFu - (unsigned)(top & 0xFFFFFFFFull));
        if (!tid) {
            g_idx[r * KNN + it] = midx;
            keys[midx] = 0;
        }
        __syncthreads();
    }
}

// ---------------- edgeconv GEMM: Y[o, pos] = sum_c W[o,c] * e(pos,c) ----------------
__global__ void edgeconv_gemm(const float* __restrict__ xin, int use_x, int choff,
                              int bstride, int Cin, const float* __restrict__ W, int Cout) {
    __shared__ float As[16][64];
    __shared__ float Bs[16][64];
    __shared__ int sB[64], sN[64], sNb[64];
    int tid = threadIdx.x;
    int pos0 = blockIdx.x * 64, o0 = blockIdx.y * 64;
    if (tid < 64) {
        int pos = pos0 + tid;
        int bn = pos / KNN;
        int k = pos - bn * KNN;
        sB[tid] = bn >> 11;
        sN[tid] = bn & 2047;
        sNb[tid] = g_idx[bn * KNN + k];
    }
    __syncthreads();
    const float* fb = use_x ? xin : g_H;
    int twoC = 2 * Cin;
    int tx = tid & 15, ty = tid >> 4;
    float acc[4][4] = {};
    for (int c0 = 0; c0 < twoC; c0 += 16) {
#pragma unroll
        for (int l = 0; l < 4; l++) {
            int li = l * 256 + tid;
            int cl = li >> 6, m = li & 63;
            int c = c0 + cl;
            float v = 0.f;
            if (c < Cin) {
                const float* fp = fb + (size_t)sB[m] * bstride + (size_t)(choff + c) * N_PTS;
                v = fp[sNb[m]] - fp[sN[m]];
            } else if (c < twoC) {
                const float* fp =
                    fb + (size_t)sB[m] * bstride + (size_t)(choff + c - Cin) * N_PTS;
                v = fp[sN[m]];
            }
            As[cl][m] = v;
            Bs[cl][m] = (c < twoC) ? W[(size_t)(o0 + m) * twoC + c] : 0.f;
        }
        __syncthreads();
#pragma unroll
        for (int kk = 0; kk < 16; kk++) {
            float4 a4 = *(const float4*)&As[kk][ty << 2];
            float4 b4 = *(const float4*)&Bs[kk][tx << 2];
            float a[4] = {a4.x, a4.y, a4.z, a4.w};
            float bb[4] = {b4.x, b4.y, b4.z, b4.w};
#pragma unroll
            for (int i = 0; i < 4; i++)
#pragma unroll
                for (int j = 0; j < 4; j++) acc[i][j] += a[i] * bb[j];
        }
        __syncthreads();
    }
#pragma unroll
    for (int j = 0; j < 4; j++) {
        int o = o0 + (tx << 2) + j;
        float4 v = make_float4(acc[0][j], acc[1][j], acc[2][j], acc[3][j]);
        *(float4*)&g_Y[(size_t)o * PPOS + pos0 + (ty << 2)] = v;
    }
}

// ---------------- conv5 GEMM: Y5[o, pos] = sum_c W5[o,c] * H[b,c,n] ----------------
__global__ void conv5_gemm(const float* __restrict__ W) {
    __shared__ float As[16][64];
    __shared__ float Bs[16][64];
    int tid = threadIdx.x;
    int pos0 = blockIdx.x * 64, o0 = blockIdx.y * 64;
    int b = pos0 >> 11, n0 = pos0 & 2047;
    int tx = tid & 15, ty = tid >> 4;
    float acc[4][4] = {};
    for (int c0 = 0; c0 < HCH; c0 += 16) {
#pragma unroll
        for (int l = 0; l < 4; l++) {
            int li = l * 256 + tid;
            int cl = li >> 6, m = li & 63;
            As[cl][m] = g_H[(size_t)b * HCH * N_PTS + (size_t)(c0 + cl) * N_PTS + n0 + m];
            Bs[cl][m] = W[(size_t)(o0 + m) * HCH + c0 + cl];
        }
        __syncthreads();
#pragma unroll
        for (int kk = 0; kk < 16; kk++) {
            float4 a4 = *(const float4*)&As[kk][ty << 2];
            float4 b4 = *(const float4*)&Bs[kk][tx << 2];
            float a[4] = {a4.x, a4.y, a4.z, a4.w};
            float bb[4] = {b4.x, b4.y, b4.z, b4.w};
#pragma unroll
            for (int i = 0; i < 4; i++)
#pragma unroll
                for (int j = 0; j < 4; j++) acc[i][j] += a[i] * bb[j];
        }
        __syncthreads();
    }
#pragma unroll
    for (int j = 0; j < 4; j++) {
        int o = o0 + (tx << 2) + j;
        float4 v = make_float4(acc[0][j], acc[1][j], acc[2][j], acc[3][j]);
        *(float4*)&g_Y5[(size_t)o * 8192 + pos0 + (ty << 2)] = v;
    }
}

// ---------------- BN batch statistics (double accumulation) ----------------
__global__ void zero_stats() {
    int t = threadIdx.x;
    g_sum[t] = 0.0;
    g_sq[t] = 0.0;
}

__global__ void stats_kernel(int which, int P, int CH) {
    int o = blockIdx.x;
    const float* Y = (which ? g_Y5 : g_Y);
    size_t base = (size_t)o * P + (size_t)blockIdx.y * CH;
    double s = 0.0, q = 0.0;
    for (int i = threadIdx.x; i < CH; i += 256) {
        double v = (double)Y[base + i];
        s += v;
        q += v * v;
    }
    __shared__ double sh[256];
    int tid = threadIdx.x;
    sh[tid] = s;
    __syncthreads();
    for (int st = 128; st; st >>= 1) {
        if (tid < st) sh[tid] += sh[tid + st];
        __syncthreads();
    }
    double tot_s = sh[0];
    __syncthreads();
    sh[tid] = q;
    __syncthreads();
    for (int st = 128; st; st >>= 1) {
        if (tid < st) sh[tid] += sh[tid + st];
        __syncthreads();
    }
    if (!tid) {
        atomicAdd(&g_sum[o], tot_s);
        atomicAdd(&g_sq[o], sh[0]);
    }
}

__global__ void finalize_bn(const float* __restrict__ gam, const float* __restrict__ bet,
                            int Cout, double cnt) {
    int o = blockIdx.x * blockDim.x + threadIdx.x;
    if (o >= Cout) return;
    double m = g_sum[o] / cnt;
    double v = g_sq[o] / cnt - m * m;
    float sc = (float)((double)gam[o] / sqrt(v + 1e-5));
    g_scale[o] = sc;
    g_shift[o] = bet[o] - (float)m * sc;
}

// ---------------- BN + LeakyReLU + max over k -> f_next in g_H ----------------
__global__ void bnmax_kernel(int Cout, int dstoff) {
    int bn = blockIdx.x;
    int b = bn >> 11, n = bn & 2047;
    int lane = threadIdx.x & 31, w = threadIdx.x >> 5;
    for (int o = w; o < Cout; o += 4) {
        float v = -1e30f;
        if (lane < KNN) {
            float y = g_Y[(size_t)o * PPOS + (size_t)bn * KNN + lane];
            v = y * g_scale[o] + g_shift[o];
            v = v > 0.f ? v : NEG_SLOPE * v;
        }
#pragma unroll
        for (int s = 16; s; s >>= 1) v = fmaxf(v, __shfl_xor_sync(0xffffffffu, v, s));
        if (!lane)
            g_H[(size_t)b * HCH * N_PTS + (size_t)(dstoff + o) * N_PTS + n] = v;
    }
}

// ---------------- conv5 BN + LReLU + max & mean over N -> z ----------------
__global__ void zmaxmean_kernel() {
    int o = blockIdx.x, b = blockIdx.y;
    const float* row = g_Y5 + (size_t)o * 8192 + (size_t)b * 2048;
    float sc = g_scale[o], sh = g_shift[o];
    float mx = -1e30f, sm = 0.f;
    for (int n = threadIdx.x; n < 2048; n += 256) {
        float v = row[n] * sc + sh;
        v = v > 0.f ? v : NEG_SLOPE * v;
        mx = fmaxf(mx, v);
        sm += v;
    }
    __shared__ float smx[256];
    __shared__ float ssm[256];
    int tid = threadIdx.x;
    smx[tid] = mx;
    ssm[tid] = sm;
    __syncthreads();
    for (int st = 128; st; st >>= 1) {
        if (tid < st) {
            smx[tid] = fmaxf(smx[tid], smx[tid + st]);
            ssm[tid] += ssm[tid + st];
        }
        __syncthreads();
    }
    if (!tid) {
        g_z[b * 2048 + o] = smx[0];
        g_z[b * 2048 + 1024 + o] = ssm[0] * (1.f / 2048.f);
    }
}

// ---------------- MLP head: z -> e (B,10) ----------------
__global__ void head_kernel(const float* __restrict__ lw1, const float* __restrict__ lb1,
                            const float* __restrict__ lw2, const float* __restrict__ lb2,
                            const float* __restrict__ lw3, const float* __restrict__ lb3,
                            int slot, float* __restrict__ out) {
    int b = blockIdx.x, tid = threadIdx.x;
    __shared__ float zs[2048];
    __shared__ float z1[256];
    __shared__ float z2[64];
    for (int i = tid; i < 2048; i += 256) zs[i] = g_z[b * 2048 + i];
    __syncthreads();
    {
        float a = lb1[tid];
        const float* wr = lw1 + (size_t)tid * 2048;
        for (int c = 0; c < 2048; c++) a += wr[c] * zs[c];
        z1[tid] = a;
    }
    __syncthreads();
    if (tid < 64) {
        float a = lb2[tid];
        const float* wr = lw2 + (size_t)tid * 256;
        for (int c = 0; c < 256; c++) a += wr[c] * z1[c];
        z2[tid] = a;
    }
    __syncthreads();
    if (tid < 10) {
        float a = lb3[tid];
        const float* wr = lw3 + (size_t)tid * 64;
        for (int c = 0; c < 64; c++) a += wr[c] * z2[c];
        g_e[slot * 40 + b * 10 + tid] = a;
        out[6404 + slot * 40 + b * 10 + tid] = a;
    }
}

// ---------------- cluster assignment q, x_dis ----------------
__global__ void cluster_kernel(const float* __restrict__ cw, int slot,
                               float* __restrict__ out) {
    int b = blockIdx.x, j = threadIdx.x;
    __shared__ float es[10];
    __shared__ float red[1024];
    if (j < 10) es[j] = g_e[slot * 40 + b * 10 + j];
    __syncthreads();
    float xd = 0.f, qn = 0.f;
    if (j < 800) {
#pragma unroll
        for (int t = 0; t < 10; t++) {
            float d = es[t] - cw[j * 10 + t];
            xd += d * d;
        }
        qn = 1.f / (1.f + xd);  // (1+xd/alpha)^(-(alpha+1)/2), alpha=1
    }
    red[j] = qn;
    __syncthreads();
    for (int st = 512; st; st >>= 1) {
        if (j < st) red[j] += red[j + st];
        __syncthreads();
    }
    float tot = red[0];
    if (j < 800) {
        out[4 + slot * 3200 + b * 800 + j] = qn / tot;
        if (!slot) out[6484 + b * 800 + j] = xd;
    }
}

// ---------------- sim = ||e1 - e2 + 1e-6|| ----------------
__global__ void sim_kernel(float* __restrict__ out) {
    int b = threadIdx.x;
    if (b < 4) {
        float s = 0.f;
        for (int j = 0; j < 10; j++) {
            float d = g_e[b * 10 + j] - g_e[40 + b * 10 + j] + 1e-6f;
            s += d * d;
        }
        out[b] = sqrtf(s);
    }
}

// ---------------- host orchestration ----------------
extern "C" void kernel_launch(void* const* d_in, const int* in_sizes, int n_in,
                              void* d_out, int out_size) {
    const float* x1 = (const float*)d_in[0];
    const float* x2 = (const float*)d_in[1];
    const float* Wl[4] = {(const float*)d_in[2], (const float*)d_in[5],
                          (const float*)d_in[8], (const float*)d_in[11]};
    const float* Gl[4] = {(const float*)d_in[3], (const float*)d_in[6],
                          (const float*)d_in[9], (const float*)d_in[12]};
    const float* Bl[4] = {(const float*)d_in[4], (const float*)d_in[7],
                          (const float*)d_in[10], (const float*)d_in[13]};
    const float* w5 = (const float*)d_in[14];
    const float* g5 = (const float*)d_in[15];
    const float* b5 = (const float*)d_in[16];
    const float* lw1 = (const float*)d_in[17];
    const float* lb1 = (const float*)d_in[18];
    const float* lw2 = (const float*)d_in[19];
    const float* lb2 = (const float*)d_in[20];
    const float* lw3 = (const float*)d_in[21];
    const float* lb3 = (const float*)d_in[22];
    const float* cw = (const float*)d_in[23];
    float* out = (float*)d_out;

    const int Cin[4] = {3, 64, 64, 128};
    const int Cout[4] = {64, 64, 128, 256};
    const int choff[4] = {0, 0, 64, 128};
    const int dstoff[4] = {0, 64, 128, 256};

    for (int s = 0; s < 2; s++) {
        const float* x = s ? x2 : x1;
        for (int l = 0; l < 4; l++) {
            int use_x = (l == 0) ? 1 : 0;
            int bstride = use_x ? 3 * N_PTS : HCH * N_PTS;
            compute_xx<<<(B_SZ * N_PTS + 255) / 256, 256>>>(x, use_x, choff[l], bstride,
                                                            Cin[l]);
            pd_gemm<<<dim3(32, 32, 4), 256>>>(x, use_x, choff[l], bstride, Cin[l]);
            topk_kernel<<<B_SZ * N_PTS, 256>>>();
            edgeconv_gemm<<<dim3(PPOS / 64, Cout[l] / 64), 256>>>(
                x, use_x, choff[l], bstride, Cin[l], Wl[l], Cout[l]);
            zero_stats<<<1, 1024>>>();
            stats_kernel<<<dim3(Cout[l], 10), 256>>>(0, PPOS, PPOS / 10);
            finalize_bn<<<(Cout[l] + 255) / 256, 256>>>(Gl[l], Bl[l], Cout[l],
                                                        (double)PPOS);
            bnmax_kernel<<<B_SZ * N_PTS, 128>>>(Cout[l], dstoff[l]);
        }
        conv5_gemm<<<dim3(8192 / 64, 1024 / 64), 256>>>(w5);
        zero_stats<<<1, 1024>>>();
        stats_kernel<<<dim3(1024, 1), 256>>>(1, 8192, 8192);
        finalize_bn<<<(1024 + 255) / 256, 256>>>(g5, b5, 1024, 8192.0);
        zmaxmean_kernel<<<dim3(1024, 4), 256>>>();
        head_kernel<<<4, 256>>>(lw1, lb1, lw2, lb2, lw3, lb3, s, out);
        cluster_kernel<<<4, 1024>>>(cw, s, out);
    }
    sim_kernel<<<1, 32>>>(out);
}

// round 2
// speedup vs baseline: 2.2405x; 2.2405x over previous
#include <cuda_runtime.h>
#include <math.h>

#define N_PTS 2048
#define B_SZ 4
#define NB (B_SZ * N_PTS)          // 8192 positions
#define KNN 20
#define PPOS (NB * KNN)            // 163840
#define HCH 512
#define NEG_SLOPE 0.2f

// ---------------- scratch (static device globals) ----------------
__device__ float  g_pd[B_SZ * N_PTS * N_PTS];   // 64 MB
__device__ float  g_xx[NB];
__device__ int    g_idx[NB * KNN];
__device__ float  g_Xt[NB * 4];                 // pos-major x, padded stride 4
__device__ float  g_Ht[NB * HCH];               // pos-major features [bn][512]
__device__ float  g_Wpq[512 * 128];             // packed [W1 ; W2-W1]
__device__ float  g_PQ[512 * NB + 8];           // P rows then Q rows, o-major
__device__ float  g_M[256 * NB];                // maxP + Q per (o, bn)
__device__ float  g_Y5[1024 * NB];              // conv5 pre-BN output
__device__ double g_sum[1024], g_sq[1024];
__device__ float  g_scale[1024], g_shift[1024];
__device__ float  g_z[B_SZ * 2048];
__device__ float  g_e[2 * B_SZ * 10];

// ---------------- build pos-major x with zero pad ----------------
__global__ void transpose_x(const float* __restrict__ x) {
    int i = blockIdx.x * 256 + threadIdx.x;
    if (i >= NB) return;
    int b = i >> 11, n = i & 2047;
    float4 v;
    v.x = x[(b * 3 + 0) * N_PTS + n];
    v.y = x[(b * 3 + 1) * N_PTS + n];
    v.z = x[(b * 3 + 2) * N_PTS + n];
    v.w = 0.f;
    *(float4*)&g_Xt[i * 4] = v;
}

// ---------------- xx[bn] = sum_c F[bn][c]^2 ----------------
__global__ void compute_xx(const float* __restrict__ F, int ldf, int K) {
    int i = blockIdx.x * 256 + threadIdx.x;
    if (i >= NB) return;
    const float* row = F + (size_t)i * ldf;
    float s = 0.f;
    for (int c = 0; c < K; c++) { float v = row[c]; s += v * v; }
    g_xx[i] = s;
}

// ---------------- pd GEMM: pd[b][n][m] = 2*<F_n,F_m> - xx_n - xx_m ----------------
// tiles 128x128, BK=16, 256 threads, 8x8 microtile, double-buffered
__global__ __launch_bounds__(256, 2) void pd_gemm2(const float* __restrict__ F, int ldf,
                                                   int rowLen, int K, size_t bstride) {
    __shared__ float As[2][16][132];
    __shared__ float Bs[2][16][132];
    int tid = threadIdx.x, tx = tid & 15, ty = tid >> 4;
    int n0 = blockIdx.y * 128, m0 = blockIdx.x * 128;
    int b = blockIdx.z;
    const float* Ab = F + (size_t)b * bstride + (size_t)n0 * ldf;
    const float* Bb = F + (size_t)b * bstride + (size_t)m0 * ldf;
    int k4 = (tid & 3) * 4, rowq = tid >> 2;
    int KIT = (K + 15) >> 4;
    float acc[8][8] = {};
    // tile 0
    {
#pragma unroll
        for (int r = 0; r < 2; r++) {
            int rw = rowq + r * 64;
            float4 va = make_float4(0, 0, 0, 0), vb = make_float4(0, 0, 0, 0);
            if (k4 < rowLen) {
                va = *(const float4*)&Ab[(size_t)rw * ldf + k4];
                vb = *(const float4*)&Bb[(size_t)rw * ldf + k4];
            }
            As[0][k4 + 0][rw] = va.x; As[0][k4 + 1][rw] = va.y;
            As[0][k4 + 2][rw] = va.z; As[0][k4 + 3][rw] = va.w;
            Bs[0][k4 + 0][rw] = vb.x; Bs[0][k4 + 1][rw] = vb.y;
            Bs[0][k4 + 2][rw] = vb.z; Bs[0][k4 + 3][rw] = vb.w;
        }
    }
    __syncthreads();
    int buf = 0;
    for (int it = 0; it < KIT; ++it) {
        float4 ra[2], rb[2];
        bool more = (it + 1 < KIT);
        if (more) {
            int k0 = (it + 1) << 4;
#pragma unroll
            for (int r = 0; r < 2; r++) {
                int rw = rowq + r * 64;
                ra[r] = make_float4(0, 0, 0, 0);
                rb[r] = make_float4(0, 0, 0, 0);
                if (k0 + k4 < rowLen) {
                    ra[r] = *(const float4*)&Ab[(size_t)rw * ldf + k0 + k4];
                    rb[r] = *(const float4*)&Bb[(size_t)rw * ldf + k0 + k4];
                }
            }
        }
#pragma unroll
        for (int k = 0; k < 16; k++) {
            float4 a0 = *(const float4*)&As[buf][k][ty * 4];
            float4 a1 = *(const float4*)&As[buf][k][64 + ty * 4];
            float4 b0 = *(const float4*)&Bs[buf][k][tx * 4];
            float4 b1 = *(const float4*)&Bs[buf][k][64 + tx * 4];
            float av[8] = {a0.x, a0.y, a0.z, a0.w, a1.x, a1.y, a1.z, a1.w};
            float bv[8] = {b0.x, b0.y, b0.z, b0.w, b1.x, b1.y, b1.z, b1.w};
#pragma unroll
            for (int i = 0; i < 8; i++)
#pragma unroll
                for (int j = 0; j < 8; j++) acc[i][j] += av[i] * bv[j];
        }
        if (more) {
            int nb2 = buf ^ 1;
#pragma unroll
            for (int r = 0; r < 2; r++) {
                int rw = rowq + r * 64;
                As[nb2][k4 + 0][rw] = ra[r].x; As[nb2][k4 + 1][rw] = ra[r].y;
                As[nb2][k4 + 2][rw] = ra[r].z; As[nb2][k4 + 3][rw] = ra[r].w;
                Bs[nb2][k4 + 0][rw] = rb[r].x; Bs[nb2][k4 + 1][rw] = rb[r].y;
                Bs[nb2][k4 + 2][rw] = rb[r].z; Bs[nb2][k4 + 3][rw] = rb[r].w;
            }
            __syncthreads();
            buf = nb2;
        }
    }
#pragma unroll
    for (int i = 0; i < 8; i++) {
        int n = n0 + (i < 4 ? ty * 4 + i : 64 + ty * 4 + (i - 4));
        float xn = g_xx[b * N_PTS + n];
        float4 v0, v1;
        int mA = m0 + tx * 4, mB = m0 + 64 + tx * 4;
        v0.x = 2.f * acc[i][0] - xn - g_xx[b * N_PTS + mA + 0];
        v0.y = 2.f * acc[i][1] - xn - g_xx[b * N_PTS + mA + 1];
        v0.z = 2.f * acc[i][2] - xn - g_xx[b * N_PTS + mA + 2];
        v0.w = 2.f * acc[i][3] - xn - g_xx[b * N_PTS + mA + 3];
        v1.x = 2.f * acc[i][4] - xn - g_xx[b * N_PTS + mB + 0];
        v1.y = 2.f * acc[i][5] - xn - g_xx[b * N_PTS + mB + 1];
        v1.z = 2.f * acc[i][6] - xn - g_xx[b * N_PTS + mB + 2];
        v1.w = 2.f * acc[i][7] - xn - g_xx[b * N_PTS + mB + 3];
        size_t base = (size_t)b * N_PTS * N_PTS + (size_t)n * N_PTS;
        *(float4*)&g_pd[base + mA] = v0;
        *(float4*)&g_pd[base + mB] = v1;
    }
}

// ---------------- generic GEMM: C[m][n] = sum_k A[m][k]*B[n][k] ----------------
// A scalar-guarded loads (weights), B pos-major float4 rows. 128x128 tiles.
__global__ __launch_bounds__(256, 2) void sgemm_wn(const float* __restrict__ A, int lda,
                                                   int K, const float* __restrict__ B,
                                                   int ldb, int rowLenB,
                                                   float* __restrict__ C, int ldc) {
    __shared__ float As[2][16][132];
    __shared__ float Bs[2][16][132];
    int tid = threadIdx.x, tx = tid & 15, ty = tid >> 4;
    int n0 = blockIdx.x * 128, m0 = blockIdx.y * 128;
    const float* Ab = A + (size_t)m0 * lda;
    const float* Bb = B + (size_t)n0 * ldb;
    int k4 = (tid & 3) * 4, rowq = tid >> 2;
    int KIT = (K + 15) >> 4;
    float acc[8][8] = {};
    {
#pragma unroll
        for (int r = 0; r < 8; r++) {
            int m = tx + r * 16;
            As[0][ty][m] = (ty < K) ? Ab[(size_t)m * lda + ty] : 0.f;
        }
#pragma unroll
        for (int r = 0; r < 2; r++) {
            int rw = rowq + r * 64;
            float4 v = make_float4(0, 0, 0, 0);
            if (k4 < rowLenB) v = *(const float4*)&Bb[(size_t)rw * ldb + k4];
            Bs[0][k4 + 0][rw] = v.x; Bs[0][k4 + 1][rw] = v.y;
            Bs[0][k4 + 2][rw] = v.z; Bs[0][k4 + 3][rw] = v.w;
        }
    }
    __syncthreads();
    int buf = 0;
    for (int it = 0; it < KIT; ++it) {
        float ra[8];
        float4 rb[2];
        bool more = (it + 1 < KIT);
        if (more) {
            int k0 = (it + 1) << 4;
#pragma unroll
            for (int r = 0; r < 8; r++) {
                int m = tx + r * 16;
                ra[r] = (k0 + ty < K) ? Ab[(size_t)m * lda + k0 + ty] : 0.f;
            }
#pragma unroll
            for (int r = 0; r < 2; r++) {
                int rw = rowq + r * 64;
                rb[r] = make_float4(0, 0, 0, 0);
                if (k0 + k4 < rowLenB) rb[r] = *(const float4*)&Bb[(size_t)rw * ldb + k0 + k4];
            }
        }
#pragma unroll
        for (int k = 0; k < 16; k++) {
            float4 a0 = *(const float4*)&As[buf][k][ty * 4];
            float4 a1 = *(const float4*)&As[buf][k][64 + ty * 4];
            float4 b0 = *(const float4*)&Bs[buf][k][tx * 4];
            float4 b1 = *(const float4*)&Bs[buf][k][64 + tx * 4];
            float av[8] = {a0.x, a0.y, a0.z, a0.w, a1.x, a1.y, a1.z, a1.w};
            float bv[8] = {b0.x, b0.y, b0.z, b0.w, b1.x, b1.y, b1.z, b1.w};
#pragma unroll
            for (int i = 0; i < 8; i++)
#pragma unroll
                for (int j = 0; j < 8; j++) acc[i][j] += av[i] * bv[j];
        }
        if (more) {
            int nb2 = buf ^ 1;
#pragma unroll
            for (int r = 0; r < 8; r++) As[nb2][ty][tx + r * 16] = ra[r];
#pragma unroll
            for (int r = 0; r < 2; r++) {
                int rw = rowq + r * 64;
                Bs[nb2][k4 + 0][rw] = rb[r].x; Bs[nb2][k4 + 1][rw] = rb[r].y;
                Bs[nb2][k4 + 2][rw] = rb[r].z; Bs[nb2][k4 + 3][rw] = rb[r].w;
            }
            __syncthreads();
            buf = nb2;
        }
    }
#pragma unroll
    for (int i = 0; i < 8; i++) {
        int m = m0 + (i < 4 ? ty * 4 + i : 64 + ty * 4 + (i - 4));
        float4 v0 = make_float4(acc[i][0], acc[i][1], acc[i][2], acc[i][3]);
        float4 v1 = make_float4(acc[i][4], acc[i][5], acc[i][6], acc[i][7]);
        *(float4*)&C[(size_t)m * ldc + n0 + tx * 4] = v0;
        *(float4*)&C[(size_t)m * ldc + n0 + 64 + tx * 4] = v1;
    }
}

// ---------------- top-20 per row (value desc, index asc on ties) ----------------
__global__ void topk_kernel() {
    int r = blockIdx.x;
    const float* row = g_pd + (size_t)r * N_PTS;
    __shared__ unsigned long long keys[N_PTS];
    __shared__ unsigned long long red[256];
    int tid = threadIdx.x;
    for (int m = tid; m < N_PTS; m += 256) {
        unsigned u = __float_as_uint(row[m]);
        u = (u & 0x80000000u) ? ~u : (u | 0x80000000u);
        keys[m] = ((unsigned long long)u << 32) | (unsigned)(0xFFFFFFFFu - m);
    }
    __syncthreads();
    for (int it = 0; it < KNN; it++) {
        unsigned long long best = 0;
        for (int m = tid; m < N_PTS; m += 256) {
            unsigned long long k = keys[m];
            if (k > best) best = k;
        }
        red[tid] = best;
        __syncthreads();
        for (int st = 128; st; st >>= 1) {
            if (tid < st && red[tid + st] > red[tid]) red[tid] = red[tid + st];
            __syncthreads();
        }
        unsigned long long top = red[0];
        int midx = (int)(0xFFFFFFFFu - (unsigned)(top & 0xFFFFFFFFull));
        if (!tid) {
            g_idx[r * KNN + it] = midx;
            keys[midx] = 0;
        }
        __syncthreads();
    }
}

// ---------------- pack [W1 ; W2-W1] ----------------
__global__ void build_wpq(const float* __restrict__ W, int Cout, int Cin) {
    int i = blockIdx.x * 256 + threadIdx.x;
    if (i >= Cout * Cin) return;
    int o = i / Cin, c = i - o * Cin;
    float w1 = W[(size_t)o * 2 * Cin + c];
    float w2 = W[(size_t)o * 2 * Cin + Cin + c];
    g_Wpq[(size_t)o * Cin + c] = w1;
    g_Wpq[(size_t)(Cout + o) * Cin + c] = w2 - w1;
}

// ---------------- neighbor reduce: stats + M = max_k P[nb] + Q ----------------
__global__ void nbr_reduce(int Cout) {
    int o = blockIdx.x, b = blockIdx.y;
    __shared__ float sp[N_PTS];
    __shared__ double rs1[256], rs2[256];
    int tid = threadIdx.x;
    const float* Prow = g_PQ + (size_t)o * NB + b * N_PTS;
    const float* Qrow = g_PQ + (size_t)(Cout + o) * NB + b * N_PTS;
    for (int i = tid; i < N_PTS; i += 256) sp[i] = Prow[i];
    __syncthreads();
    double s1 = 0.0, s2 = 0.0;
    for (int n = tid; n < N_PTS; n += 256) {
        const int* ip = g_idx + (size_t)(b * N_PTS + n) * KNN;
        float mx = -1e30f, su = 0.f, su2 = 0.f;
#pragma unroll
        for (int k = 0; k < KNN; k++) {
            float p = sp[ip[k]];
            mx = fmaxf(mx, p);
            su += p;
            su2 += p * p;
        }
        float q = Qrow[n];
        g_M[(size_t)o * NB + b * N_PTS + n] = mx + q;
        s1 += (double)su + 20.0 * (double)q;
        s2 += (double)su2 + 2.0 * (double)q * (double)su + 20.0 * (double)q * (double)q;
    }
    rs1[tid] = s1;
    rs2[tid] = s2;
    __syncthreads();
    for (int st = 128; st; st >>= 1) {
        if (tid < st) { rs1[tid] += rs1[tid + st]; rs2[tid] += rs2[tid + st]; }
        __syncthreads();
    }
    if (!tid) {
        atomicAdd(&g_sum[o], rs1[0]);
        atomicAdd(&g_sq[o], rs2[0]);
    }
}

__global__ void zero_stats() {
    int t = threadIdx.x;
    g_sum[t] = 0.0;
    g_sq[t] = 0.0;
}

__global__ void finalize_bn(const float* __restrict__ gam, const float* __restrict__ bet,
                            int Cout, double cnt) {
    int o = blockIdx.x * 256 + threadIdx.x;
    if (o >= Cout) return;
    double m = g_sum[o] / cnt;
    double v = g_sq[o] / cnt - m * m;
    float sc = (float)((double)gam[o] / sqrt(v + 1e-5));
    g_scale[o] = sc;
    g_shift[o] = bet[o] - (float)m * sc;
}

// ---------------- apply BN+LReLU to M -> Ht (pos-major) ----------------
__global__ void apply_bn(int Cout, int dstoff) {
    int bn = blockIdx.x;
    for (int o = threadIdx.x; o < Cout; o += blockDim.x) {
        float v = g_M[(size_t)o * NB + bn] * g_scale[o] + g_shift[o];
        v = v > 0.f ? v : NEG_SLOPE * v;
        g_Ht[(size_t)bn * HCH + dstoff + o] = v;
    }
}

// ---------------- conv5 stats ----------------
__global__ void stats_y5() {
    int o = blockIdx.x;
    size_t base = (size_t)o * NB + blockIdx.y * 1024;
    double s = 0.0, q = 0.0;
    for (int i = threadIdx.x; i < 1024; i += 256) {
        double v = (double)g_Y5[base + i];
        s += v;
        q += v * v;
    }
    __shared__ double sh[256];
    int tid = threadIdx.x;
    sh[tid] = s;
    __syncthreads();
    for (int st = 128; st; st >>= 1) {
        if (tid < st) sh[tid] += sh[tid + st];
        __syncthreads();
    }
    double ts = sh[0];
    __syncthreads();
    sh[tid] = q;
    __syncthreads();
    for (int st = 128; st; st >>= 1) {
        if (tid < st) sh[tid] += sh[tid + st];
        __syncthreads();
    }
    if (!tid) {
        atomicAdd(&g_sum[o], ts);
        atomicAdd(&g_sq[o], sh[0]);
    }
}

// ---------------- conv5 BN + LReLU + max & mean over N -> z ----------------
__global__ void zmaxmean_kernel() {
    int o = blockIdx.x, b = blockIdx.y;
    const float* row = g_Y5 + (size_t)o * NB + (size_t)b * N_PTS;
    float sc = g_scale[o], sh = g_shift[o];
    float mx = -1e30f, sm = 0.f;
    for (int n = threadIdx.x; n < N_PTS; n += 256) {
        float v = row[n] * sc + sh;
        v = v > 0.f ? v : NEG_SLOPE * v;
        mx = fmaxf(mx, v);
        sm += v;
    }
    __shared__ float smx[256];
    __shared__ float ssm[256];
    int tid = threadIdx.x;
    smx[tid] = mx;
    ssm[tid] = sm;
    __syncthreads();
    for (int st = 128; st; st >>= 1) {
        if (tid < st) {
            smx[tid] = fmaxf(smx[tid], smx[tid + st]);
            ssm[tid] += ssm[tid + st];
        }
        __syncthreads();
    }
    if (!tid) {
        g_z[b * 2048 + o] = smx[0];
        g_z[b * 2048 + 1024 + o] = ssm[0] * (1.f / 2048.f);
    }
}

// ---------------- MLP head ----------------
__global__ void head_kernel(const float* __restrict__ lw1, const float* __restrict__ lb1,
                            const float* __restrict__ lw2, const float* __restrict__ lb2,
                            const float* __restrict__ lw3, const float* __restrict__ lb3,
                            int slot, float* __restrict__ out) {
    int b = blockIdx.x, tid = threadIdx.x;
    __shared__ float zs[2048];
    __shared__ float z1[256];
    __shared__ float z2[64];
    for (int i = tid; i < 2048; i += 256) zs[i] = g_z[b * 2048 + i];
    __syncthreads();
    {
        float a = lb1[tid];
        const float* wr = lw1 + (size_t)tid * 2048;
        for (int c = 0; c < 2048; c++) a += wr[c] * zs[c];
        z1[tid] = a;
    }
    __syncthreads();
    if (tid < 64) {
        float a = lb2[tid];
        const float* wr = lw2 + (size_t)tid * 256;
        for (int c = 0; c < 256; c++) a += wr[c] * z1[c];
        z2[tid] = a;
    }
    __syncthreads();
    if (tid < 10) {
        float a = lb3[tid];
        const float* wr = lw3 + (size_t)tid * 64;
        for (int c = 0; c < 64; c++) a += wr[c] * z2[c];
        g_e[slot * 40 + b * 10 + tid] = a;
        out[6404 + slot * 40 + b * 10 + tid] = a;
    }
}

// ---------------- cluster assignment ----------------
__global__ void cluster_kernel(const float* __restrict__ cw, int slot,
                               float* __restrict__ out) {
    int b = blockIdx.x, j = threadIdx.x;
    __shared__ float es[10];
    __shared__ float red[1024];
    if (j < 10) es[j] = g_e[slot * 40 + b * 10 + j];
    __syncthreads();
    float xd = 0.f, qn = 0.f;
    if (j < 800) {
#pragma unroll
        for (int t = 0; t < 10; t++) {
            float d = es[t] - cw[j * 10 + t];
            xd += d * d;
        }
        qn = 1.f / (1.f + xd);
    }
    red[j] = qn;
    __syncthreads();
    for (int st = 512; st; st >>= 1) {
        if (j < st) red[j] += red[j + st];
        __syncthreads();
    }
    float tot = red[0];
    if (j < 800) {
        out[4 + slot * 3200 + b * 800 + j] = qn / tot;
        if (!slot) out[6484 + b * 800 + j] = xd;
    }
}

__global__ void sim_kernel(float* __restrict__ out) {
    int b = threadIdx.x;
    if (b < 4) {
        float s = 0.f;
        for (int j = 0; j < 10; j++) {
            float d = g_e[b * 10 + j] - g_e[40 + b * 10 + j] + 1e-6f;
            s += d * d;
        }
        out[b] = sqrtf(s);
    }
}

// ---------------- host orchestration ----------------
extern "C" void kernel_launch(void* const* d_in, const int* in_sizes, int n_in,
                              void* d_out, int out_size) {
    const float* x1 = (const float*)d_in[0];
    const float* x2 = (const float*)d_in[1];
    const float* Wl[4] = {(const float*)d_in[2], (const float*)d_in[5],
                          (const float*)d_in[8], (const float*)d_in[11]};
    const float* Gl[4] = {(const float*)d_in[3], (const float*)d_in[6],
                          (const float*)d_in[9], (const float*)d_in[12]};
    const float* Bl[4] = {(const float*)d_in[4], (const float*)d_in[7],
                          (const float*)d_in[10], (const float*)d_in[13]};
    const float* w5 = (const float*)d_in[14];
    const float* g5 = (const float*)d_in[15];
    const float* b5 = (const float*)d_in[16];
    const float* lw1 = (const float*)d_in[17];
    const float* lb1 = (const float*)d_in[18];
    const float* lw2 = (const float*)d_in[19];
    const float* lb2 = (const float*)d_in[20];
    const float* lw3 = (const float*)d_in[21];
    const float* lb3 = (const float*)d_in[22];
    const float* cw = (const float*)d_in[23];
    float* out = (float*)d_out;

    const int Cin[4] = {3, 64, 64, 128};
    const int Cout[4] = {64, 64, 128, 256};
    const int choff[4] = {0, 0, 64, 128};
    const int dstoff[4] = {0, 64, 128, 256};

    float* xtp = nullptr;
    float* htp = nullptr;
    cudaGetSymbolAddress((void**)&xtp, g_Xt);
    cudaGetSymbolAddress((void**)&htp, g_Ht);

    for (int s = 0; s < 2; s++) {
        const float* x = s ? x2 : x1;
        transpose_x<<<NB / 256, 256>>>(x);
        for (int l = 0; l < 4; l++) {
            const float* F = (l == 0) ? xtp : (htp + choff[l]);
            int ldf = (l == 0) ? 4 : HCH;
            int rowLen = (l == 0) ? 4 : Cin[l];
            size_t bstride = (size_t)N_PTS * ldf;
            compute_xx<<<NB / 256, 256>>>(F, ldf, Cin[l]);
            pd_gemm2<<<dim3(16, 16, 4), 256>>>(F, ldf, rowLen, Cin[l], bstride);
            topk_kernel<<<NB, 256>>>();
            build_wpq<<<(Cout[l] * Cin[l] + 255) / 256, 256>>>(Wl[l], Cout[l], Cin[l]);
            {
                float* wpq = nullptr;
                float* pq = nullptr;
                cudaGetSymbolAddress((void**)&wpq, g_Wpq);
                cudaGetSymbolAddress((void**)&pq, g_PQ);
                sgemm_wn<<<dim3(NB / 128, 2 * Cout[l] / 128), 256>>>(
                    wpq, Cin[l], Cin[l], F, ldf, rowLen, pq, NB);
            }
            zero_stats<<<1, 1024>>>();
            nbr_reduce<<<dim3(Cout[l], B_SZ), 256>>>(Cout[l]);
            finalize_bn<<<1, 256>>>(Gl[l], Bl[l], Cout[l], (double)PPOS);
            apply_bn<<<NB, 256>>>(Cout[l], dstoff[l]);
        }
        {
            float* y5 = nullptr;
            cudaGetSymbolAddress((void**)&y5, g_Y5);
            sgemm_wn<<<dim3(NB / 128, 1024 / 128), 256>>>(w5, HCH, HCH, htp, HCH, HCH,
                                                          y5, NB);
        }
        zero_stats<<<1, 1024>>>();
        stats_y5<<<dim3(1024, 8), 256>>>();
        finalize_bn<<<4, 256>>>(g5, b5, 1024, (double)NB);
        zmaxmean_kernel<<<dim3(1024, 4), 256>>>();
        head_kernel<<<4, 256>>>(lw1, lb1, lw2, lb2, lw3, lb3, s, out);
        cluster_kernel<<<4, 1024>>>(cw, s, out);
    }
    sim_kernel<<<1, 32>>>(out);
}

// round 4
// speedup vs baseline: 2.7514x; 1.2280x over previous
#include <cuda_runtime.h>
#include <math.h>

#define N_PTS 2048
#define B_SZ 4
#define NB (B_SZ * N_PTS)          // 8192 positions
#define KNN 20
#define PPOS (NB * KNN)            // 163840
#define HCH 512
#define NEG_SLOPE 0.2f

// ---------------- scratch (static device globals) ----------------
__device__ float  g_pd[B_SZ * N_PTS * N_PTS];   // 64 MB
__device__ float  g_xx[NB];
__device__ int    g_idx[NB * KNN];
__device__ float  g_Xt[NB * 4];                 // pos-major x, padded stride 4
__device__ float  g_Ht[NB * HCH];               // pos-major features [bn][512]
__device__ float  g_Wpq[512 * 128];             // packed [W1 ; W2-W1]
__device__ float  g_PQ[512 * NB + 8];           // P rows then Q rows, o-major
__device__ float  g_M[256 * NB];                // maxP + Q per (o, bn)
__device__ float  g_Y5[1024 * NB];              // conv5 pre-BN output
__device__ double g_sum[1024], g_sq[1024];
__device__ float  g_scale[1024], g_shift[1024];
__device__ float  g_z[B_SZ * 2048];
__device__ float  g_e[2 * B_SZ * 10];

// ---------------- build pos-major x with zero pad ----------------
__global__ void transpose_x(const float* __restrict__ x) {
    int i = blockIdx.x * 256 + threadIdx.x;
    if (i >= NB) return;
    int b = i >> 11, n = i & 2047;
    float4 v;
    v.x = x[(b * 3 + 0) * N_PTS + n];
    v.y = x[(b * 3 + 1) * N_PTS + n];
    v.z = x[(b * 3 + 2) * N_PTS + n];
    v.w = 0.f;
    *(float4*)&g_Xt[i * 4] = v;
}

// ---------------- xx[bn] = sum_c F[bn][c]^2 ----------------
__global__ void compute_xx(const float* __restrict__ F, int ldf, int K) {
    int i = blockIdx.x * 256 + threadIdx.x;
    if (i >= NB) return;
    const float* row = F + (size_t)i * ldf;
    float s = 0.f;
    for (int c = 0; c < K; c++) { float v = row[c]; s += v * v; }
    g_xx[i] = s;
}

// ---------------- pd GEMM: pd[b][n][m] = 2*<F_n,F_m> - xx_n - xx_m ----------------
__global__ __launch_bounds__(256, 2) void pd_gemm2(const float* __restrict__ F, int ldf,
                                                   int rowLen, int K, size_t bstride) {
    __shared__ float As[2][16][132];
    __shared__ float Bs[2][16][132];
    int tid = threadIdx.x, tx = tid & 15, ty = tid >> 4;
    int n0 = blockIdx.y * 128, m0 = blockIdx.x * 128;
    int b = blockIdx.z;
    const float* Ab = F + (size_t)b * bstride + (size_t)n0 * ldf;
    const float* Bb = F + (size_t)b * bstride + (size_t)m0 * ldf;
    int k4 = (tid & 3) * 4, rowq = tid >> 2;
    int KIT = (K + 15) >> 4;
    float acc[8][8] = {};
    {
#pragma unroll
        for (int r = 0; r < 2; r++) {
            int rw = rowq + r * 64;
            float4 va = make_float4(0, 0, 0, 0), vb = make_float4(0, 0, 0, 0);
            if (k4 < rowLen) {
                va = *(const float4*)&Ab[(size_t)rw * ldf + k4];
                vb = *(const float4*)&Bb[(size_t)rw * ldf + k4];
            }
            As[0][k4 + 0][rw] = va.x; As[0][k4 + 1][rw] = va.y;
            As[0][k4 + 2][rw] = va.z; As[0][k4 + 3][rw] = va.w;
            Bs[0][k4 + 0][rw] = vb.x; Bs[0][k4 + 1][rw] = vb.y;
            Bs[0][k4 + 2][rw] = vb.z; Bs[0][k4 + 3][rw] = vb.w;
        }
    }
    __syncthreads();
    int buf = 0;
    for (int it = 0; it < KIT; ++it) {
        float4 ra[2], rb[2];
        bool more = (it + 1 < KIT);
        if (more) {
            int k0 = (it + 1) << 4;
#pragma unroll
            for (int r = 0; r < 2; r++) {
                int rw = rowq + r * 64;
                ra[r] = make_float4(0, 0, 0, 0);
                rb[r] = make_float4(0, 0, 0, 0);
                if (k0 + k4 < rowLen) {
                    ra[r] = *(const float4*)&Ab[(size_t)rw * ldf + k0 + k4];
                    rb[r] = *(const float4*)&Bb[(size_t)rw * ldf + k0 + k4];
                }
            }
        }
#pragma unroll
        for (int k = 0; k < 16; k++) {
            float4 a0 = *(const float4*)&As[buf][k][ty * 4];
            float4 a1 = *(const float4*)&As[buf][k][64 + ty * 4];
            float4 b0 = *(const float4*)&Bs[buf][k][tx * 4];
            float4 b1 = *(const float4*)&Bs[buf][k][64 + tx * 4];
            float av[8] = {a0.x, a0.y, a0.z, a0.w, a1.x, a1.y, a1.z, a1.w};
            float bv[8] = {b0.x, b0.y, b0.z, b0.w, b1.x, b1.y, b1.z, b1.w};
#pragma unroll
            for (int i = 0; i < 8; i++)
#pragma unroll
                for (int j = 0; j < 8; j++) acc[i][j] += av[i] * bv[j];
        }
        if (more) {
            int nb2 = buf ^ 1;
#pragma unroll
            for (int r = 0; r < 2; r++) {
                int rw = rowq + r * 64;
                As[nb2][k4 + 0][rw] = ra[r].x; As[nb2][k4 + 1][rw] = ra[r].y;
                As[nb2][k4 + 2][rw] = ra[r].z; As[nb2][k4 + 3][rw] = ra[r].w;
                Bs[nb2][k4 + 0][rw] = rb[r].x; Bs[nb2][k4 + 1][rw] = rb[r].y;
                Bs[nb2][k4 + 2][rw] = rb[r].z; Bs[nb2][k4 + 3][rw] = rb[r].w;
            }
            __syncthreads();
            buf = nb2;
        }
    }
#pragma unroll
    for (int i = 0; i < 8; i++) {
        int n = n0 + (i < 4 ? ty * 4 + i : 64 + ty * 4 + (i - 4));
        float xn = g_xx[b * N_PTS + n];
        float4 v0, v1;
        int mA = m0 + tx * 4, mB = m0 + 64 + tx * 4;
        v0.x = 2.f * acc[i][0] - xn - g_xx[b * N_PTS + mA + 0];
        v0.y = 2.f * acc[i][1] - xn - g_xx[b * N_PTS + mA + 1];
        v0.z = 2.f * acc[i][2] - xn - g_xx[b * N_PTS + mA + 2];
        v0.w = 2.f * acc[i][3] - xn - g_xx[b * N_PTS + mA + 3];
        v1.x = 2.f * acc[i][4] - xn - g_xx[b * N_PTS + mB + 0];
        v1.y = 2.f * acc[i][5] - xn - g_xx[b * N_PTS + mB + 1];
        v1.z = 2.f * acc[i][6] - xn - g_xx[b * N_PTS + mB + 2];
        v1.w = 2.f * acc[i][7] - xn - g_xx[b * N_PTS + mB + 3];
        size_t base = (size_t)b * N_PTS * N_PTS + (size_t)n * N_PTS;
        *(float4*)&g_pd[base + mA] = v0;
        *(float4*)&g_pd[base + mB] = v1;
    }
}

// ---------------- generic GEMM: C[m][n] = sum_k A[m][k]*B[n][k] ----------------
__global__ __launch_bounds__(256, 2) void sgemm_wn(const float* __restrict__ A, int lda,
                                                   int K, const float* __restrict__ B,
                                                   int ldb, int rowLenB,
                                                   float* __restrict__ C, int ldc) {
    __shared__ float As[2][16][132];
    __shared__ float Bs[2][16][132];
    int tid = threadIdx.x, tx = tid & 15, ty = tid >> 4;
    int n0 = blockIdx.x * 128, m0 = blockIdx.y * 128;
    const float* Ab = A + (size_t)m0 * lda;
    const float* Bb = B + (size_t)n0 * ldb;
    int k4 = (tid & 3) * 4, rowq = tid >> 2;
    int KIT = (K + 15) >> 4;
    float acc[8][8] = {};
    {
#pragma unroll
        for (int r = 0; r < 8; r++) {
            int m = tx + r * 16;
            As[0][ty][m] = (ty < K) ? Ab[(size_t)m * lda + ty] : 0.f;
        }
#pragma unroll
        for (int r = 0; r < 2; r++) {
            int rw = rowq + r * 64;
            float4 v = make_float4(0, 0, 0, 0);
            if (k4 < rowLenB) v = *(const float4*)&Bb[(size_t)rw * ldb + k4];
            Bs[0][k4 + 0][rw] = v.x; Bs[0][k4 + 1][rw] = v.y;
            Bs[0][k4 + 2][rw] = v.z; Bs[0][k4 + 3][rw] = v.w;
        }
    }
    __syncthreads();
    int buf = 0;
    for (int it = 0; it < KIT; ++it) {
        float ra[8];
        float4 rb[2];
        bool more = (it + 1 < KIT);
        if (more) {
            int k0 = (it + 1) << 4;
#pragma unroll
            for (int r = 0; r < 8; r++) {
                int m = tx + r * 16;
                ra[r] = (k0 + ty < K) ? Ab[(size_t)m * lda + k0 + ty] : 0.f;
            }
#pragma unroll
            for (int r = 0; r < 2; r++) {
                int rw = rowq + r * 64;
                rb[r] = make_float4(0, 0, 0, 0);
                if (k0 + k4 < rowLenB) rb[r] = *(const float4*)&Bb[(size_t)rw * ldb + k0 + k4];
            }
        }
#pragma unroll
        for (int k = 0; k < 16; k++) {
            float4 a0 = *(const float4*)&As[buf][k][ty * 4];
            float4 a1 = *(const float4*)&As[buf][k][64 + ty * 4];
            float4 b0 = *(const float4*)&Bs[buf][k][tx * 4];
            float4 b1 = *(const float4*)&Bs[buf][k][64 + tx * 4];
            float av[8] = {a0.x, a0.y, a0.z, a0.w, a1.x, a1.y, a1.z, a1.w};
            float bv[8] = {b0.x, b0.y, b0.z, b0.w, b1.x, b1.y, b1.z, b1.w};
#pragma unroll
            for (int i = 0; i < 8; i++)
#pragma unroll
                for (int j = 0; j < 8; j++) acc[i][j] += av[i] * bv[j];
        }
        if (more) {
            int nb2 = buf ^ 1;
#pragma unroll
            for (int r = 0; r < 8; r++) As[nb2][ty][tx + r * 16] = ra[r];
#pragma unroll
            for (int r = 0; r < 2; r++) {
                int rw = rowq + r * 64;
                Bs[nb2][k4 + 0][rw] = rb[r].x; Bs[nb2][k4 + 1][rw] = rb[r].y;
                Bs[nb2][k4 + 2][rw] = rb[r].z; Bs[nb2][k4 + 3][rw] = rb[r].w;
            }
            __syncthreads();
            buf = nb2;
        }
    }
#pragma unroll
    for (int i = 0; i < 8; i++) {
        int m = m0 + (i < 4 ? ty * 4 + i : 64 + ty * 4 + (i - 4));
        float4 v0 = make_float4(acc[i][0], acc[i][1], acc[i][2], acc[i][3]);
        float4 v1 = make_float4(acc[i][4], acc[i][5], acc[i][6], acc[i][7]);
        *(float4*)&C[(size_t)m * ldc + n0 + tx * 4] = v0;
        *(float4*)&C[(size_t)m * ldc + n0 + 64 + tx * 4] = v1;
    }
}

// ---------------- top-20 per row via bucket select ----------------
// Exact same total order as before: key = (ordered_value << 32) | (~m).
// Selected SET is written unordered (downstream reductions are permutation-
// invariant: max / sum / sum-of-squares over the k neighbors).
__global__ __launch_bounds__(256, 4) void topk_kernel() {
    int r = blockIdx.x;
    const float* row = g_pd + (size_t)r * N_PTS;
    __shared__ unsigned keys[N_PTS];
    __shared__ unsigned long long cand[N_PTS];
    __shared__ int hist[132];
    __shared__ int sB, cnts[2];  // cnts[0]=selected, cnts[1]=candidates
    int tid = threadIdx.x;
    if (tid < 132) hist[tid] = 0;
    if (tid < 2) cnts[tid] = 0;
    __syncthreads();
#pragma unroll
    for (int i = 0; i < 8; i++) {
        int m = tid + i * 256;
        unsigned u = __float_as_uint(row[m]);
        u = (u & 0x80000000u) ? ~u : (u | 0x80000000u);
        keys[m] = u;
        atomicAdd(&hist[u >> 24], 1);
    }
    __syncthreads();
    if (tid == 0) {
        int c = 0, b = 128;
        while (b > 0 && c + hist[b] < KNN) { c += hist[b]; b--; }
        sB = b;
    }
    __syncthreads();
    unsigned Bl = (unsigned)sB;
#pragma unroll
    for (int i = 0; i < 8; i++) {
        int m = tid + i * 256;
        unsigned u = keys[m];
        unsigned bk = u >> 24;
        if (bk > Bl) {
            int slot = atomicAdd(&cnts[0], 1);
            g_idx[r * KNN + slot] = m;
        } else if (bk == Bl) {
            int slot = atomicAdd(&cnts[1], 1);
            cand[slot] = ((unsigned long long)u << 32) | (unsigned)(0xFFFFFFFFu - m);
        }
    }
    __syncthreads();
    if (tid < 32) {
        int base = cnts[0];
        int cnt = cnts[1];
        int need = KNN - base;
        for (int it = 0; it < need; it++) {
            unsigned long long best = 0;
            for (int j = tid; j < cnt; j += 32) {
                unsigned long long k = cand[j];
                if (k > best) best = k;
            }
#pragma unroll
            for (int s = 16; s; s >>= 1) {
                unsigned long long o = __shfl_xor_sync(0xffffffffu, best, s);
                if (o > best) best = o;
            }
            if (tid == 0)
                g_idx[r * KNN + base + it] =
                    (int)(0xFFFFFFFFu - (unsigned)(best & 0xFFFFFFFFull));
            for (int j = tid; j < cnt; j += 32)
                if (cand[j] == best) cand[j] = 0;
            __syncwarp();
        }
    }
}

// ---------------- pack [W1 ; W2-W1] ----------------
__global__ void build_wpq(const float* __restrict__ W, int Cout, int Cin) {
    int i = blockIdx.x * 256 + threadIdx.x;
    if (i >= Cout * Cin) return;
    int o = i / Cin, c = i - o * Cin;
    float w1 = W[(size_t)o * 2 * Cin + c];
    float w2 = W[(size_t)o * 2 * Cin + Cin + c];
    g_Wpq[(size_t)o * Cin + c] = w1;
    g_Wpq[(size_t)(Cout + o) * Cin + c] = w2 - w1;
}

// ---------------- neighbor reduce: stats + M = max_k P[nb] + Q ----------------
__global__ void nbr_reduce(int Cout) {
    int o = blockIdx.x, b = blockIdx.y;
    __shared__ float sp[N_PTS];
    __shared__ double rs1[256], rs2[256];
    int tid = threadIdx.x;
    const float* Prow = g_PQ + (size_t)o * NB + b * N_PTS;
    const float* Qrow = g_PQ + (size_t)(Cout + o) * NB + b * N_PTS;
    for (int i = tid; i < N_PTS; i += 256) sp[i] = Prow[i];
    __syncthreads();
    double s1 = 0.0, s2 = 0.0;
    for (int n = tid; n < N_PTS; n += 256) {
        const int* ip = g_idx + (size_t)(b * N_PTS + n) * KNN;
        float mx = -1e30f, su = 0.f, su2 = 0.f;
#pragma unroll
        for (int k = 0; k < KNN; k++) {
            float p = sp[ip[k]];
            mx = fmaxf(mx, p);
            su += p;
            su2 += p * p;
        }
        float q = Qrow[n];
        g_M[(size_t)o * NB + b * N_PTS + n] = mx + q;
        s1 += (double)su + 20.0 * (double)q;
        s2 += (double)su2 + 2.0 * (double)q * (double)su + 20.0 * (double)q * (double)q;
    }
    rs1[tid] = s1;
    rs2[tid] = s2;
    __syncthreads();
    for (int st = 128; st; st >>= 1) {
        if (tid < st) { rs1[tid] += rs1[tid + st]; rs2[tid] += rs2[tid + st]; }
        __syncthreads();
    }
    if (!tid) {
        atomicAdd(&g_sum[o], rs1[0]);
        atomicAdd(&g_sq[o], rs2[0]);
    }
}

__global__ void zero_stats() {
    int t = threadIdx.x;
    g_sum[t] = 0.0;
    g_sq[t] = 0.0;
}

__global__ void finalize_bn(const float* __restrict__ gam, const float* __restrict__ bet,
                            int Cout, double cnt) {
    int o = blockIdx.x * 256 + threadIdx.x;
    if (o >= Cout) return;
    double m = g_sum[o] / cnt;
    double v = g_sq[o] / cnt - m * m;
    float sc = (float)((double)gam[o] / sqrt(v + 1e-5));
    g_scale[o] = sc;
    g_shift[o] = bet[o] - (float)m * sc;
}

// ---------------- apply BN+LReLU to M -> Ht (pos-major) ----------------
__global__ void apply_bn(int Cout, int dstoff) {
    int bn = blockIdx.x;
    for (int o = threadIdx.x; o < Cout; o += blockDim.x) {
        float v = g_M[(size_t)o * NB + bn] * g_scale[o] + g_shift[o];
        v = v > 0.f ? v : NEG_SLOPE * v;
        g_Ht[(size_t)bn * HCH + dstoff + o] = v;
    }
}

// ---------------- conv5 stats ----------------
__global__ void stats_y5() {
    int o = blockIdx.x;
    size_t base = (size_t)o * NB + blockIdx.y * 1024;
    double s = 0.0, q = 0.0;
    for (int i = threadIdx.x; i < 1024; i += 256) {
        double v = (double)g_Y5[base + i];
        s += v;
        q += v * v;
    }
    __shared__ double sh[256];
    int tid = threadIdx.x;
    sh[tid] = s;
    __syncthreads();
    for (int st = 128; st; st >>= 1) {
        if (tid < st) sh[tid] += sh[tid + st];
        __syncthreads();
    }
    double ts = sh[0];
    __syncthreads();
    sh[tid] = q;
    __syncthreads();
    for (int st = 128; st; st >>= 1) {
        if (tid < st) sh[tid] += sh[tid + st];
        __syncthreads();
    }
    if (!tid) {
        atomicAdd(&g_sum[o], ts);
        atomicAdd(&g_sq[o], sh[0]);
    }
}

// ---------------- conv5 BN + LReLU + max & mean over N -> z ----------------
__global__ void zmaxmean_kernel() {
    int o = blockIdx.x, b = blockIdx.y;
    const float* row = g_Y5 + (size_t)o * NB + (size_t)b * N_PTS;
    float sc = g_scale[o], sh = g_shift[o];
    float mx = -1e30f, sm = 0.f;
    for (int n = threadIdx.x; n < N_PTS; n += 256) {
        float v = row[n] * sc + sh;
        v = v > 0.f ? v : NEG_SLOPE * v;
        mx = fmaxf(mx, v);
        sm += v;
    }
    __shared__ float smx[256];
    __shared__ float ssm[256];
    int tid = threadIdx.x;
    smx[tid] = mx;
    ssm[tid] = sm;
    __syncthreads();
    for (int st = 128; st; st >>= 1) {
        if (tid < st) {
            smx[tid] = fmaxf(smx[tid], smx[tid + st]);
            ssm[tid] += ssm[tid + st];
        }
        __syncthreads();
    }
    if (!tid) {
        g_z[b * 2048 + o] = smx[0];
        g_z[b * 2048 + 1024 + o] = ssm[0] * (1.f / 2048.f);
    }
}

// ---------------- MLP head ----------------
__global__ void head_kernel(const float* __restrict__ lw1, const float* __restrict__ lb1,
                            const float* __restrict__ lw2, const float* __restrict__ lb2,
                            const float* __restrict__ lw3, const float* __restrict__ lb3,
                            int slot, float* __restrict__ out) {
    int b = blockIdx.x, tid = threadIdx.x;
    __shared__ float zs[2048];
    __shared__ float z1[256];
    __shared__ float z2[64];
    for (int i = tid; i < 2048; i += 256) zs[i] = g_z[b * 2048 + i];
    __syncthreads();
    {
        float a = lb1[tid];
        const float* wr = lw1 + (size_t)tid * 2048;
        for (int c = 0; c < 2048; c++) a += wr[c] * zs[c];
        z1[tid] = a;
    }
    __syncthreads();
    if (tid < 64) {
        float a = lb2[tid];
        const float* wr = lw2 + (size_t)tid * 256;
        for (int c = 0; c < 256; c++) a += wr[c] * z1[c];
        z2[tid] = a;
    }
    __syncthreads();
    if (tid < 10) {
        float a = lb3[tid];
        const float* wr = lw3 + (size_t)tid * 64;
        for (int c = 0; c < 64; c++) a += wr[c] * z2[c];
        g_e[slot * 40 + b * 10 + tid] = a;
        out[6404 + slot * 40 + b * 10 + tid] = a;
    }
}

// ---------------- cluster assignment ----------------
__global__ void cluster_kernel(const float* __restrict__ cw, int slot,
                               float* __restrict__ out) {
    int b = blockIdx.x, j = threadIdx.x;
    __shared__ float es[10];
    __shared__ float red[1024];
    if (j < 10) es[j] = g_e[slot * 40 + b * 10 + j];
    __syncthreads();
    float xd = 0.f, qn = 0.f;
    if (j < 800) {
#pragma unroll
        for (int t = 0; t < 10; t++) {
            float d = es[t] - cw[j * 10 + t];
            xd += d * d;
        }
        qn = 1.f / (1.f + xd);
    }
    red[j] = qn;
    __syncthreads();
    for (int st = 512; st; st >>= 1) {
        if (j < st) red[j] += red[j + st];
        __syncthreads();
    }
    float tot = red[0];
    if (j < 800) {
        out[4 + slot * 3200 + b * 800 + j] = qn / tot;
        if (!slot) out[6484 + b * 800 + j] = xd;
    }
}

__global__ void sim_kernel(float* __restrict__ out) {
    int b = threadIdx.x;
    if (b < 4) {
        float s = 0.f;
        for (int j = 0; j < 10; j++) {
            float d = g_e[b * 10 + j] - g_e[40 + b * 10 + j] + 1e-6f;
            s += d * d;
        }
        out[b] = sqrtf(s);
    }
}

// ---------------- host orchestration ----------------
extern "C" void kernel_launch(void* const* d_in, const int* in_sizes, int n_in,
                              void* d_out, int out_size) {
    const float* x1 = (const float*)d_in[0];
    const float* x2 = (const float*)d_in[1];
    const float* Wl[4] = {(const float*)d_in[2], (const float*)d_in[5],
                          (const float*)d_in[8], (const float*)d_in[11]};
    const float* Gl[4] = {(const float*)d_in[3], (const float*)d_in[6],
                          (const float*)d_in[9], (const float*)d_in[12]};
    const float* Bl[4] = {(const float*)d_in[4], (const float*)d_in[7],
                          (const float*)d_in[10], (const float*)d_in[13]};
    const float* w5 = (const float*)d_in[14];
    const float* g5 = (const float*)d_in[15];
    const float* b5 = (const float*)d_in[16];
    const float* lw1 = (const float*)d_in[17];
    const float* lb1 = (const float*)d_in[18];
    const float* lw2 = (const float*)d_in[19];
    const float* lb2 = (const float*)d_in[20];
    const float* lw3 = (const float*)d_in[21];
    const float* lb3 = (const float*)d_in[22];
    const float* cw = (const float*)d_in[23];
    float* out = (float*)d_out;

    const int Cin[4] = {3, 64, 64, 128};
    const int Cout[4] = {64, 64, 128, 256};
    const int choff[4] = {0, 0, 64, 128};
    const int dstoff[4] = {0, 64, 128, 256};

    float* xtp = nullptr;
    float* htp = nullptr;
    cudaGetSymbolAddress((void**)&xtp, g_Xt);
    cudaGetSymbolAddress((void**)&htp, g_Ht);

    for (int s = 0; s < 2; s++) {
        const float* x = s ? x2 : x1;
        transpose_x<<<NB / 256, 256>>>(x);
        for (int l = 0; l < 4; l++) {
            const float* F = (l == 0) ? xtp : (htp + choff[l]);
            int ldf = (l == 0) ? 4 : HCH;
            int rowLen = (l == 0) ? 4 : Cin[l];
            size_t bstride = (size_t)N_PTS * ldf;
            compute_xx<<<NB / 256, 256>>>(F, ldf, Cin[l]);
            pd_gemm2<<<dim3(16, 16, 4), 256>>>(F, ldf, rowLen, Cin[l], bstride);
            topk_kernel<<<NB, 256>>>();
            build_wpq<<<(Cout[l] * Cin[l] + 255) / 256, 256>>>(Wl[l], Cout[l], Cin[l]);
            {
                float* wpq = nullptr;
                float* pq = nullptr;
                cudaGetSymbolAddress((void**)&wpq, g_Wpq);
                cudaGetSymbolAddress((void**)&pq, g_PQ);
                sgemm_wn<<<dim3(NB / 128, 2 * Cout[l] / 128), 256>>>(
                    wpq, Cin[l], Cin[l], F, ldf, rowLen, pq, NB);
            }
            zero_stats<<<1, 1024>>>();
            nbr_reduce<<<dim3(Cout[l], B_SZ), 256>>>(Cout[l]);
            finalize_bn<<<1, 256>>>(Gl[l], Bl[l], Cout[l], (double)PPOS);
            apply_bn<<<NB, 256>>>(Cout[l], dstoff[l]);
        }
        {
            float* y5 = nullptr;
            cudaGetSymbolAddress((void**)&y5, g_Y5);
            sgemm_wn<<<dim3(NB / 128, 1024 / 128), 256>>>(w5, HCH, HCH, htp, HCH, HCH,
                                                          y5, NB);
        }
        zero_stats<<<1, 1024>>>();
        stats_y5<<<dim3(1024, 8), 256>>>();
        finalize_bn<<<4, 256>>>(g5, b5, 1024, (double)NB);
        zmaxmean_kernel<<<dim3(1024, 4), 256>>>();
        head_kernel<<<4, 256>>>(lw1, lb1, lw2, lb2, lw3, lb3, s, out);
        cluster_kernel<<<4, 1024>>>(cw, s, out);
    }
    sim_kernel<<<1, 32>>>(out);
}